// round 1
// baseline (speedup 1.0000x reference)
#include <cuda_runtime.h>

// Problem constants
#define NB 64
#define NT 512
#define NM 8
#define NV 50
#define TPB 128
#define TILES 2   // NT / (2*TPB)

__device__ __forceinline__ unsigned long long pk2(float x, float y){
  unsigned long long r; asm("mov.b64 %0, {%1,%2};" : "=l"(r) : "f"(x), "f"(y)); return r;
}
__device__ __forceinline__ void up2(unsigned long long v, float &x, float &y){
  asm("mov.b64 {%0,%1}, %2;" : "=f"(x), "=f"(y) : "l"(v));
}
__device__ __forceinline__ unsigned long long ffma2(unsigned long long a, unsigned long long b, unsigned long long c){
  unsigned long long d;
  asm("fma.rn.f32x2 %0, %1, %2, %3;" : "=l"(d) : "l"(a), "l"(b), "l"(c));
  return d;
}
__device__ __forceinline__ unsigned long long fadd2(unsigned long long a, unsigned long long b){
  unsigned long long d;
  asm("add.rn.f32x2 %0, %1, %2;" : "=l"(d) : "l"(a), "l"(b));
  return d;
}
__device__ __forceinline__ float ex2f(float x){ float r; asm("ex2.approx.f32 %0, %1;" : "=f"(r) : "f"(x)); return r; }
__device__ __forceinline__ float rcpf(float x){ float r; asm("rcp.approx.f32 %0, %1;" : "=f"(r) : "f"(x)); return r; }

__global__ void __launch_bounds__(TPB)
ima_kernel(const float* __restrict__ x,  const float* __restrict__ PA,
           const float* __restrict__ conv_w, const float* __restrict__ conv_b,
           const float* __restrict__ bn_gamma, const float* __restrict__ bn_beta,
           const float* __restrict__ bn_mean,  const float* __restrict__ bn_var,
           const float* __restrict__ w1, const float* __restrict__ b1,
           const float* __restrict__ w2, const float* __restrict__ b2,
           float* __restrict__ out)
{
  const int blk  = blockIdx.x;           // 0 .. NB*NM*TILES-1
  const int tile = blk & (TILES - 1);
  const int bm   = blk / TILES;
  const int m    = bm & (NM - 1);
  const int b    = bm / NM;

  // PA[m] staged transposed ([w][v]) and pair-duplicated {p,p} for f32x2 FMA.
  __shared__ unsigned long long sPA[NV * NV];   // 20 KB
  for (int i = threadIdx.x; i < NV * NV; i += TPB){
    int v = i / NV, w = i - v * NV;             // read coalesced over w
    float p = PA[(m * NV + v) * NV + w];
    sPA[w * NV + v] = pk2(p, p);
  }

  // Fold conv (scalar) + BN (eval) into h = relu(fma(agg, A, C))
  const float scale = bn_gamma[m] * rsqrtf(bn_var[m] + 1e-5f);
  const float A = conv_w[m] * scale;
  const float C = (conv_b[m] - bn_mean[m]) * scale + bn_beta[m];

  // MLP params, pre-folded for base-2 exponentials.
  // tanh(z) = 1 - 2/(exp(2z)+1); exp(2z) = ex2( h*(2*log2e*w1) + 2*log2e*b1 )
  // score kept in log2 domain: s_l2 = log2e * (b2 + sum_j w2_j * tanh_j)
  const float LOG2E = 1.4426950408889634f;
  float w1e[8], b1e[8], w2n[8];
  float s0 = b2[m];
  #pragma unroll
  for (int j = 0; j < 8; j++){
    w1e[j] = 2.f * LOG2E * w1[m * 8 + j];
    b1e[j] = 2.f * LOG2E * b1[m * 8 + j];
    float wj = w2[m * 8 + j];
    s0 += wj;                       // sum contributes the "+1" part of tanh
    w2n[j] = 2.f * LOG2E * wj;      // coefficient of the -2/(e+1) part, log2-scaled
  }
  s0 *= LOG2E;
  __syncthreads();

  // Each thread owns two adjacent timesteps t0, t0+1 (packed lanes).
  const int t0 = tile * (2 * TPB) + 2 * threadIdx.x;
  const float* xb = x + ((size_t)(b * NM * NV + m * NV)) * NT + t0;

  unsigned long long xm[NV];
  #pragma unroll
  for (int v = 0; v < NV; v++){
    float2 val = *reinterpret_cast<const float2*>(xb + (size_t)v * NT);
    xm[v] = pk2(val.x, val.y);
  }

  // Online softmax state per lane
  float mx0 = -1e30f, mx1 = -1e30f;
  float l0 = 0.f, l1 = 0.f;
  float a0 = 0.f, a1 = 0.f;

  #pragma unroll 1
  for (int w = 0; w < NV; w++){
    const unsigned long long* row = &sPA[w * NV];
    unsigned long long acc0 = pk2(0.f, 0.f);
    unsigned long long acc1 = pk2(0.f, 0.f);
    #pragma unroll
    for (int v = 0; v < NV; v += 2){
      acc0 = ffma2(xm[v],     row[v],     acc0);
      acc1 = ffma2(xm[v + 1], row[v + 1], acc1);
    }
    float gx, gy;
    up2(fadd2(acc0, acc1), gx, gy);

    // ---- lane 0 ----
    {
      float h = fmaxf(fmaf(gx, A, C), 0.f);
      float s = s0;
      #pragma unroll
      for (int j = 0; j < 8; j++){
        float e = ex2f(fmaf(h, w1e[j], b1e[j]));
        s = fmaf(-w2n[j], rcpf(e + 1.f), s);
      }
      float nm = fmaxf(mx0, s);
      float cc = ex2f(mx0 - nm);
      float pp = ex2f(s - nm);
      l0 = fmaf(l0, cc, pp);
      a0 = fmaf(a0, cc, h * pp);
      mx0 = nm;
    }
    // ---- lane 1 ----
    {
      float h = fmaxf(fmaf(gy, A, C), 0.f);
      float s = s0;
      #pragma unroll
      for (int j = 0; j < 8; j++){
        float e = ex2f(fmaf(h, w1e[j], b1e[j]));
        s = fmaf(-w2n[j], rcpf(e + 1.f), s);
      }
      float nm = fmaxf(mx1, s);
      float cc = ex2f(mx1 - nm);
      float pp = ex2f(s - nm);
      l1 = fmaf(l1, cc, pp);
      a1 = fmaf(a1, cc, h * pp);
      mx1 = nm;
    }
  }

  float2 o;
  o.x = a0 / l0;
  o.y = a1 / l1;
  *reinterpret_cast<float2*>(out + (size_t)(b * NM + m) * NT + t0) = o;
}

extern "C" void kernel_launch(void* const* d_in, const int* in_sizes, int n_in,
                              void* d_out, int out_size)
{
  (void)in_sizes; (void)n_in; (void)out_size;
  ima_kernel<<<NB * NM * TILES, TPB>>>(
      (const float*)d_in[0],  (const float*)d_in[1],
      (const float*)d_in[2],  (const float*)d_in[3],
      (const float*)d_in[4],  (const float*)d_in[5],
      (const float*)d_in[6],  (const float*)d_in[7],
      (const float*)d_in[8],  (const float*)d_in[9],
      (const float*)d_in[10], (const float*)d_in[11],
      (float*)d_out);
}

// round 2
// speedup vs baseline: 1.2244x; 1.2244x over previous
#include <cuda_runtime.h>
#include <math.h>

#define NB 64
#define NT 512
#define NM 8
#define NV 50
#define TPB 128
#define TILES 2          // NT / (2*TPB)
#define LUTN 2048
#define LUTF 2048.0f

typedef unsigned long long u64;

// Per-module score LUT: entry i = { f(u_i) - M_bound,  f(u_{i+1}) - f(u_i) }
// where u = h/(1+h), f = log2e * (b2 + sum_j w2_j * tanh(h*w1_j + b1_j)).
__device__ float2 g_lut[NM][LUTN];

__device__ __forceinline__ u64 pk2(float x, float y){
  u64 r; asm("mov.b64 %0, {%1,%2};" : "=l"(r) : "f"(x), "f"(y)); return r;
}
__device__ __forceinline__ void up2(u64 v, float &x, float &y){
  asm("mov.b64 {%0,%1}, %2;" : "=f"(x), "=f"(y) : "l"(v));
}
__device__ __forceinline__ u64 ffma2(u64 a, u64 b, u64 c){
  u64 d; asm("fma.rn.f32x2 %0, %1, %2, %3;" : "=l"(d) : "l"(a), "l"(b), "l"(c));
  return d;
}
__device__ __forceinline__ u64 fadd2(u64 a, u64 b){
  u64 d; asm("add.rn.f32x2 %0, %1, %2;" : "=l"(d) : "l"(a), "l"(b));
  return d;
}
__device__ __forceinline__ float ex2f(float x){ float r; asm("ex2.approx.f32 %0, %1;" : "=f"(r) : "f"(x)); return r; }
__device__ __forceinline__ float rcpf(float x){ float r; asm("rcp.approx.f32 %0, %1;" : "=f"(r) : "f"(x)); return r; }

// ---------------- LUT builder (one block per module) ----------------
__global__ void lut_build(const float* __restrict__ w1, const float* __restrict__ b1,
                          const float* __restrict__ w2, const float* __restrict__ b2)
{
  const int m = blockIdx.x;
  const float LOG2E = 1.4426950408889634f;
  float W1[8], B1[8], W2[8];
  float bias = b2[m];
  float M = bias;        // analytic upper bound on the raw score
  float lim = bias;      // h -> inf limit
  #pragma unroll
  for (int j = 0; j < 8; j++){
    W1[j] = w1[m*8+j]; B1[j] = b1[m*8+j]; W2[j] = w2[m*8+j];
    M += fabsf(W2[j]);
    lim += W2[j] * (W1[j] > 0.f ? 1.f : (W1[j] < 0.f ? -1.f : tanhf(B1[j])));
  }
  M   *= LOG2E;
  lim *= LOG2E;

  for (int i = threadIdx.x; i < LUTN; i += blockDim.x){
    float f0, f1;
    {
      float u = (float)i / LUTF;
      float h = u / (1.f - u);
      float s = bias;
      #pragma unroll
      for (int j = 0; j < 8; j++) s += W2[j] * tanhf(fmaf(h, W1[j], B1[j]));
      f0 = s * LOG2E;
    }
    if (i + 1 == LUTN){
      f1 = lim;
    } else {
      float u = (float)(i + 1) / LUTF;
      float h = u / (1.f - u);
      float s = bias;
      #pragma unroll
      for (int j = 0; j < 8; j++) s += W2[j] * tanhf(fmaf(h, W1[j], B1[j]));
      f1 = s * LOG2E;
    }
    g_lut[m][i] = make_float2(f0 - M, f1 - f0);
  }
}

// ---------------- main kernel ----------------
__device__ __forceinline__ void node_update(float g, float A, float C,
                                            const float2* __restrict__ sLUT,
                                            float &l, float &acc)
{
  float h = fmaxf(fmaf(g, A, C), 0.f);
  float r = rcpf(1.f + h);
  float q = fmaf(r, -LUTF, LUTF);        // u * LUTN, u = 1 - 1/(1+h)
  int   i = (int)q;                      // trunc == floor (q >= 0)
  i = min(max(i, 0), LUTN - 1);
  float fr = q - (float)i;
  float2 e = sLUT[i];
  float p = ex2f(fmaf(fr, e.y, e.x));    // exp2(score - bound), in (0,1]
  l += p;
  acc = fmaf(h, p, acc);
}

__global__ void __launch_bounds__(TPB)
ima_kernel(const float* __restrict__ x,  const float* __restrict__ PA,
           const float* __restrict__ conv_w, const float* __restrict__ conv_b,
           const float* __restrict__ bn_gamma, const float* __restrict__ bn_beta,
           const float* __restrict__ bn_mean,  const float* __restrict__ bn_var,
           float* __restrict__ out)
{
  const int blk  = blockIdx.x;           // 0 .. NB*NM*TILES-1
  const int tile = blk & (TILES - 1);
  const int bm   = blk / TILES;
  const int m    = bm & (NM - 1);
  const int b    = bm / NM;

  // PA transposed [w][v-pair], each entry = { {p0,p0}, {p1,p1} } for f32x2 FMA.
  __shared__ ulonglong2 sPA[NV][NV/2];   // 50*25*16B = 20 KB
  __shared__ float2 sLUT[LUTN];          // 16 KB

  for (int i = threadIdx.x; i < NV * (NV/2); i += TPB){
    int w = i / (NV/2), vp = i - w * (NV/2);
    float p0 = PA[(m * NV + 2*vp    ) * NV + w];
    float p1 = PA[(m * NV + 2*vp + 1) * NV + w];
    ulonglong2 e; e.x = pk2(p0, p0); e.y = pk2(p1, p1);
    sPA[w][vp] = e;
  }
  for (int i = threadIdx.x; i < LUTN; i += TPB)
    sLUT[i] = g_lut[m][i];

  // Fold conv (scalar) + BN (eval): h = relu(fma(agg, A, C))
  const float scale = bn_gamma[m] * rsqrtf(bn_var[m] + 1e-5f);
  const float A = conv_w[m] * scale;
  const float C = (conv_b[m] - bn_mean[m]) * scale + bn_beta[m];
  __syncthreads();

  // Each thread owns two adjacent timesteps t0, t0+1 (packed lanes).
  const int t0 = tile * (2 * TPB) + 2 * threadIdx.x;
  const float* xb = x + ((size_t)(b * NM * NV + m * NV)) * NT + t0;

  u64 xm[NV];
  #pragma unroll
  for (int v = 0; v < NV; v++){
    float2 val = *reinterpret_cast<const float2*>(xb + (size_t)v * NT);
    xm[v] = pk2(val.x, val.y);
  }

  float l0 = 0.f, l1 = 0.f, a0 = 0.f, a1 = 0.f;

  #pragma unroll 1
  for (int w = 0; w < NV; w++){
    const ulonglong2* row = sPA[w];
    u64 c0 = 0ULL, c1 = 0ULL, c2 = 0ULL, c3 = 0ULL;
    #pragma unroll
    for (int vp = 0; vp < NV/2 - 1; vp += 2){
      ulonglong2 e0 = row[vp];
      ulonglong2 e1 = row[vp + 1];
      c0 = ffma2(xm[2*vp    ], e0.x, c0);
      c1 = ffma2(xm[2*vp + 1], e0.y, c1);
      c2 = ffma2(xm[2*vp + 2], e1.x, c2);
      c3 = ffma2(xm[2*vp + 3], e1.y, c3);
    }
    {
      ulonglong2 e = row[NV/2 - 1];
      c0 = ffma2(xm[NV - 2], e.x, c0);
      c1 = ffma2(xm[NV - 1], e.y, c1);
    }
    float gx, gy;
    up2(fadd2(fadd2(c0, c2), fadd2(c1, c3)), gx, gy);

    node_update(gx, A, C, sLUT, l0, a0);
    node_update(gy, A, C, sLUT, l1, a1);
  }

  float2 o;
  o.x = a0 / l0;
  o.y = a1 / l1;
  *reinterpret_cast<float2*>(out + (size_t)(b * NM + m) * NT + t0) = o;
}

extern "C" void kernel_launch(void* const* d_in, const int* in_sizes, int n_in,
                              void* d_out, int out_size)
{
  (void)in_sizes; (void)n_in; (void)out_size;
  lut_build<<<NM, 256>>>((const float*)d_in[8],  (const float*)d_in[9],
                         (const float*)d_in[10], (const float*)d_in[11]);
  ima_kernel<<<NB * NM * TILES, TPB>>>(
      (const float*)d_in[0],  (const float*)d_in[1],
      (const float*)d_in[2],  (const float*)d_in[3],
      (const float*)d_in[4],  (const float*)d_in[5],
      (const float*)d_in[6],  (const float*)d_in[7],
      (float*)d_out);
}